// round 5
// baseline (speedup 1.0000x reference)
#include <cuda_runtime.h>
#include <math.h>

// ---------------------------------------------------------------------------
// Problem constants (fixed shapes)
// ---------------------------------------------------------------------------
#define BATCH 4
#define CIN   512
#define CC    256   // C = Cin/2
#define CQ    32    // Cq = C/8
#define NN    4096  // H*W
#define COUT  512

// Scratch layout (floats) in one big __device__ array
#define OFF_Q1  0
#define OFF_K1  (1*BATCH*CQ*NN)
#define OFF_Q2  (2*BATCH*CQ*NN)
#define OFF_K2  (3*BATCH*CQ*NN)
#define OFF_V1  (4*BATCH*CQ*NN)
#define OFF_V2  (OFF_V1 + BATCH*CC*NN)
#define OFF_CAT (OFF_V2 + BATCH*CC*NN)
#define SCRATCH_TOTAL (OFF_CAT + BATCH*CIN*NN)

__device__ __align__(16) float g_scratch[SCRATCH_TOTAL];

// ---------------------------------------------------------------------------
// Packed fp32x2 helpers (sm_100+ FFMA2 path; bit-exact fp32)
// ---------------------------------------------------------------------------
typedef unsigned long long ull;

__device__ __forceinline__ void fma2(ull& d, ull a, ull b) {
    asm("fma.rn.f32x2 %0, %1, %2, %3;" : "=l"(d) : "l"(a), "l"(b), "l"(d));
}
__device__ __forceinline__ ull mul2(ull a, ull b) {
    ull r; asm("mul.rn.f32x2 %0, %1, %2;" : "=l"(r) : "l"(a), "l"(b)); return r;
}
__device__ __forceinline__ ull pack2(float x, float y) {
    ull r; asm("mov.b64 %0, {%1, %2};" : "=l"(r) : "f"(x), "f"(y)); return r;
}
__device__ __forceinline__ float2 unpack2(ull v) {
    float2 r; asm("mov.b64 {%0, %1}, %2;" : "=f"(r.x), "=f"(r.y) : "l"(v)); return r;
}

// ---------------------------------------------------------------------------
// Shared GEMM body: Y tile 32(O) x 256(N), K=Kd, f32x2 inner product.
// acc pairs over adjacent n (packed operand straight from float4 halves).
// ---------------------------------------------------------------------------
__device__ __forceinline__
void gemm_tile_body(const float* __restrict__ W, const float* __restrict__ bias,
                    const float* __restrict__ Xb, float* __restrict__ Yb,
                    int Kd, int o0, int n0,
                    const float* __restrict__ gamma, const float* __restrict__ beta,
                    int fuse,
                    float Ws[32][32], float Xs[32][256])
{
    const int t  = threadIdx.x;
    const int tx = t & 31;
    const int ty = t >> 5;

    ull acc[4][4];   // [o_i][n-pair: tx4+{0,1},{2,3},128+{0,1},128+{2,3}]
#pragma unroll
    for (int i = 0; i < 4; i++)
#pragma unroll
        for (int j = 0; j < 4; j++) acc[i][j] = 0ull;

    for (int k0 = 0; k0 < Kd; k0 += 32) {
        // W tile: 32x32, 4 floats/thread
        {
            int l = t * 4;
            int r = l >> 5, c = l & 31;
            *(float4*)&Ws[r][c] = *(const float4*)(W + (long)(o0 + r) * Kd + k0 + c);
        }
        // X tile: 32x256, 8 float4/thread, fully coalesced
#pragma unroll
        for (int u = 0; u < 8; u++) {
            int f = t + 256 * u;
            int r = f >> 6;
            int c = (f & 63) * 4;
            *(float4*)&Xs[r][c] = *(const float4*)(Xb + (long)(k0 + r) * NN + n0 + c);
        }
        __syncthreads();

#pragma unroll
        for (int kk = 0; kk < 32; kk++) {
            ulonglong2 xa = *(const ulonglong2*)&Xs[kk][tx * 4];
            ulonglong2 xb = *(const ulonglong2*)&Xs[kk][tx * 4 + 128];
#pragma unroll
            for (int i = 0; i < 4; i++) {
                float wv = Ws[ty * 4 + i][kk];
                ull wd = pack2(wv, wv);
                fma2(acc[i][0], wd, xa.x);
                fma2(acc[i][1], wd, xa.y);
                fma2(acc[i][2], wd, xb.x);
                fma2(acc[i][3], wd, xb.y);
            }
        }
        __syncthreads();
    }

    const float inv_bn = rsqrtf(1.0f + 1e-5f);
#pragma unroll
    for (int i = 0; i < 4; i++) {
        int o = o0 + ty * 4 + i;
        float bv = bias[o];
        float g = 1.f, be = 0.f;
        if (fuse) { g = gamma[o] * inv_bn; be = beta[o]; }
        float v[8];
        float2 u0 = unpack2(acc[i][0]);
        float2 u1 = unpack2(acc[i][1]);
        float2 u2 = unpack2(acc[i][2]);
        float2 u3 = unpack2(acc[i][3]);
        v[0] = u0.x; v[1] = u0.y; v[2] = u1.x; v[3] = u1.y;
        v[4] = u2.x; v[5] = u2.y; v[6] = u3.x; v[7] = u3.y;
#pragma unroll
        for (int j = 0; j < 8; j++) {
            float y = v[j] + bv;
            if (fuse) {
                y = y * g + be;
                y = (y > 0.f) ? y : 0.2f * y;
            }
            v[j] = y;
        }
        float4 r0 = make_float4(v[0], v[1], v[2], v[3]);
        float4 r1 = make_float4(v[4], v[5], v[6], v[7]);
        *(float4*)(Yb + (long)o * NN + n0 + tx * 4)       = r0;
        *(float4*)(Yb + (long)o * NN + n0 + tx * 4 + 128) = r1;
    }
}

// ---------------------------------------------------------------------------
// All six projections in ONE launch. grid = (16, 20, BATCH).
//   blockIdx.y 0..3  : q1, k1, q2, k2 (Cq=32, single o-tile)
//   blockIdx.y 4..11 : v1 o-tiles 0..7
//   blockIdx.y 12..19: v2 o-tiles 0..7
// ---------------------------------------------------------------------------
__global__ __launch_bounds__(256)
void proj_kernel(const float* __restrict__ x,
                 const float* __restrict__ Wq1, const float* __restrict__ bq1,
                 const float* __restrict__ Wk1, const float* __restrict__ bk1,
                 const float* __restrict__ Wv1, const float* __restrict__ bv1,
                 const float* __restrict__ Wq2, const float* __restrict__ bq2,
                 const float* __restrict__ Wk2, const float* __restrict__ bk2,
                 const float* __restrict__ Wv2, const float* __restrict__ bv2,
                 float* __restrict__ sb)
{
    __shared__ float Ws[32][32];
    __shared__ float Xs[32][256];

    const int sy = blockIdx.y;
    const int bz = blockIdx.z;
    const int n0 = blockIdx.x * 256;
    const long XB = (long)bz * CIN * NN;

    const float *W, *bias, *Xb;
    float* Yb;
    int o0;

    if (sy < 4) {
        o0 = 0;
        switch (sy) {
            case 0:  W = Wq1; bias = bq1; Xb = x;           Yb = sb + OFF_Q1; break;
            case 1:  W = Wk1; bias = bk1; Xb = x;           Yb = sb + OFF_K1; break;
            case 2:  W = Wq2; bias = bq2; Xb = x + CC * NN; Yb = sb + OFF_Q2; break;
            default: W = Wk2; bias = bk2; Xb = x + CC * NN; Yb = sb + OFF_K2; break;
        }
        Xb += XB;
        Yb += (long)bz * CQ * NN;
    } else {
        int v  = sy - 4;
        int br = v >> 3;
        o0 = (v & 7) * 32;
        W    = br ? Wv2 : Wv1;
        bias = br ? bv2 : bv1;
        Xb   = x + (long)br * CC * NN + XB;
        Yb   = sb + (br ? OFF_V2 : OFF_V1) + (long)bz * CC * NN;
    }

    gemm_tile_body(W, bias, Xb, Yb, CC, o0, n0, nullptr, nullptr, 0, Ws, Xs);
}

// ---------------------------------------------------------------------------
// Final 1x1 conv (K=512) + BN(eval) + LeakyReLU fused
// ---------------------------------------------------------------------------
__global__ __launch_bounds__(256)
void outconv_kernel(const float* __restrict__ W, const float* __restrict__ bias,
                    const float* __restrict__ X, float* __restrict__ Y,
                    const float* __restrict__ gamma, const float* __restrict__ beta)
{
    __shared__ float Ws[32][32];
    __shared__ float Xs[32][256];

    const int n0 = blockIdx.x * 256;
    const int o0 = blockIdx.y * 32;
    const float* Xb = X + (long)blockIdx.z * CIN * NN;
    float*       Yb = Y + (long)blockIdx.z * COUT * NN;

    gemm_tile_body(W, bias, Xb, Yb, CIN, o0, n0, gamma, beta, 1, Ws, Xs);
}

// ---------------------------------------------------------------------------
// Fused flash cross-attention, fp32 with packed f32x2 FMAs.
// Per block: 64 queries, 512 threads. Streams 64-key tiles. d=32, Cv=256.
// PV pairs over the reduction dim j -> both operands packed for free.
// O accumulator: 4q x 8c packed pairs per thread (lo=even j, hi=odd j).
// ---------------------------------------------------------------------------
struct __align__(16) AttnSmem {
    float Qs[32][64];     //  8 KB   Q[d][i]
    float Ks[32][64];     //  8 KB   K[d][j]
    float Vs[256][68];    // 68 KB   V[c][j] (pitch 68)
    float Ps[64][68];     // 17 KB   P[i][j] (pitch 68)
    float red[64][9];     // partial max/sum per (row, jgroup), pitch 9
    float m_run[64];
    float l_run[64];
    float alpha_s[64];
};

extern __shared__ char attn_smem_raw[];

__global__ __launch_bounds__(512)
void flash_attn_kernel()
{
    AttnSmem& sm = *reinterpret_cast<AttnSmem*>(attn_smem_raw);

    const int t    = threadIdx.x;
    const int lane = t & 31;
    const int warp = t >> 5;            // 0..15
    const int n0   = blockIdx.x * 64;   // query tile
    const int a    = blockIdx.y;        // which cross-attention
    const int b    = blockIdx.z;        // batch

    const float* Q = g_scratch + (a == 0 ? OFF_Q2 : OFF_Q1) + (long)b * CQ * NN;
    const float* K = g_scratch + (a == 0 ? OFF_K1 : OFF_K2) + (long)b * CQ * NN;
    const float* V = g_scratch + (a == 0 ? OFF_V1 : OFF_V2) + (long)b * CC * NN;
    float*     Out = g_scratch + OFF_CAT + (long)b * CIN * NN + (long)a * CC * NN;

    // Load Q tile [32][64]: 1 float4/thread
    {
        int d = t >> 4, i = (t & 15) * 4;
        *(float4*)&sm.Qs[d][i] = *(const float4*)(Q + (long)d * NN + n0 + i);
    }
    if (t < 64) { sm.m_run[t] = -3.0e38f; sm.l_run[t] = 0.f; }

    ull acc2[4][8];   // [qi][cc]: lo = even-j partial, hi = odd-j partial
#pragma unroll
    for (int qi = 0; qi < 4; qi++)
#pragma unroll
        for (int cc = 0; cc < 8; cc++) acc2[qi][cc] = 0ull;

    const int si  = t & 63;       // S-stage: row i
    const int sjg = t >> 6;       // S-stage: j-group (8 keys), 0..7
    const int sjb = sjg * 8;
    const int q0  = warp * 4;     // PV-stage: query base

    for (int kt = 0; kt < 64; kt++) {
        const int m0 = kt * 64;

        // Load K tile [32][64]: 1 float4/thread
        {
            int d = t >> 4, j = (t & 15) * 4;
            *(float4*)&sm.Ks[d][j] = *(const float4*)(K + (long)d * NN + m0 + j);
        }
        // Load V tile [256 c][64 j]: 8 float4/thread, coalesced along j
        {
            int j4 = t & 15;
            int cbase = t >> 4;
#pragma unroll
            for (int r = 0; r < 8; r++) {
                int c = cbase + 32 * r;
                *(float4*)&sm.Vs[c][j4 * 4] =
                    *(const float4*)(V + (long)c * NN + m0 + j4 * 4);
            }
        }
        __syncthreads();   // (A) tiles visible

        // --- S = Q^T K : each thread 1 row x 8 cols (4 packed pairs) ---
        ull s2[4] = {0ull, 0ull, 0ull, 0ull};
#pragma unroll
        for (int d = 0; d < 32; d++) {
            float qv = sm.Qs[d][si];
            ull qd = pack2(qv, qv);
            ulonglong2 k0 = *(const ulonglong2*)&sm.Ks[d][sjb];
            ulonglong2 k1 = *(const ulonglong2*)&sm.Ks[d][sjb + 4];
            fma2(s2[0], qd, k0.x);
            fma2(s2[1], qd, k0.y);
            fma2(s2[2], qd, k1.x);
            fma2(s2[3], qd, k1.y);
        }
        float s[8];
        {
            float2 u0 = unpack2(s2[0]), u1 = unpack2(s2[1]);
            float2 u2 = unpack2(s2[2]), u3 = unpack2(s2[3]);
            s[0] = u0.x; s[1] = u0.y; s[2] = u1.x; s[3] = u1.y;
            s[4] = u2.x; s[5] = u2.y; s[6] = u3.x; s[7] = u3.y;
        }
        float tmax = s[0];
#pragma unroll
        for (int x = 1; x < 8; x++) tmax = fmaxf(tmax, s[x]);
        sm.red[si][sjg] = tmax;
        __syncthreads();   // (B) partial maxes visible

        if (t < 64) {
            float m_old = sm.m_run[t];
            float tm = sm.red[t][0];
#pragma unroll
            for (int g = 1; g < 8; g++) tm = fmaxf(tm, sm.red[t][g]);
            float m_new = fmaxf(m_old, tm);
            float al = __expf(m_old - m_new);
            sm.alpha_s[t] = al;
            sm.m_run[t]   = m_new;
            sm.l_run[t]  *= al;
        }
        __syncthreads();   // (C) m_new / alpha visible

        // --- P = exp(S - m), write to smem, partial row-sums ---
        {
            float mrow = sm.m_run[si];
            float p[8];
            float lsum = 0.f;
#pragma unroll
            for (int x = 0; x < 8; x++) {
                p[x] = __expf(s[x] - mrow);
                lsum += p[x];
            }
            *(float4*)&sm.Ps[si][sjb]     = make_float4(p[0], p[1], p[2], p[3]);
            *(float4*)&sm.Ps[si][sjb + 4] = make_float4(p[4], p[5], p[6], p[7]);
            sm.red[si][sjg] = lsum;
        }

        // Rescale accumulators by alpha (stable since barrier C)
        {
#pragma unroll
            for (int qi = 0; qi < 4; qi++) {
                float aq = sm.alpha_s[q0 + qi];
                ull a2 = pack2(aq, aq);
#pragma unroll
                for (int cc = 0; cc < 8; cc++)
                    acc2[qi][cc] = mul2(acc2[qi][cc], a2);
            }
        }
        __syncthreads();   // (D) P + partial sums visible

        if (t < 64) {
            float ls = sm.red[t][0];
#pragma unroll
            for (int g = 1; g < 8; g++) ls += sm.red[t][g];
            sm.l_run[t] += ls;
        }

        // --- O += P * V^T : 4 queries x 8 channels, j-paired f32x2 ---
#pragma unroll 2
        for (int j4 = 0; j4 < 16; j4++) {
            ulonglong2 vu[8];
#pragma unroll
            for (int cc = 0; cc < 8; cc++)
                vu[cc] = *(const ulonglong2*)&sm.Vs[lane + 32 * cc][4 * j4];
#pragma unroll
            for (int qi = 0; qi < 4; qi++) {
                ulonglong2 pu = *(const ulonglong2*)&sm.Ps[q0 + qi][4 * j4];
#pragma unroll
                for (int cc = 0; cc < 8; cc++) {
                    fma2(acc2[qi][cc], pu.x, vu[cc].x);
                    fma2(acc2[qi][cc], pu.y, vu[cc].y);
                }
            }
        }
        __syncthreads();   // (E) safe to overwrite tiles next iter
    }

    // --- Normalize (lo+hi), stage through smem for coalesced output ---
    float* stage = (float*)sm.Vs;   // 64 rows x pitch-257 fits in Vs
    {
#pragma unroll
        for (int qi = 0; qi < 4; qi++) {
            float linv = 1.0f / sm.l_run[q0 + qi];
#pragma unroll
            for (int cc = 0; cc < 8; cc++) {
                float2 u = unpack2(acc2[qi][cc]);
                stage[(q0 + qi) * 257 + lane + 32 * cc] = (u.x + u.y) * linv;
            }
        }
    }
    __syncthreads();
    {
        int qb = (t & 15) * 4;
        int cb = t >> 4;
#pragma unroll
        for (int r = 0; r < 8; r++) {
            int c = cb + 32 * r;
            float4 o;
            o.x = stage[(qb + 0) * 257 + c];
            o.y = stage[(qb + 1) * 257 + c];
            o.z = stage[(qb + 2) * 257 + c];
            o.w = stage[(qb + 3) * 257 + c];
            *(float4*)(Out + (long)c * NN + n0 + qb) = o;
        }
    }
}

// ---------------------------------------------------------------------------
// Launch
// ---------------------------------------------------------------------------
extern "C" void kernel_launch(void* const* d_in, const int* in_sizes, int n_in,
                              void* d_out, int out_size)
{
    const float* x   = (const float*)d_in[0];
    const float* Wq1 = (const float*)d_in[1];
    const float* bq1 = (const float*)d_in[2];
    const float* Wk1 = (const float*)d_in[3];
    const float* bk1 = (const float*)d_in[4];
    const float* Wv1 = (const float*)d_in[5];
    const float* bv1 = (const float*)d_in[6];
    const float* Wq2 = (const float*)d_in[7];
    const float* bq2 = (const float*)d_in[8];
    const float* Wk2 = (const float*)d_in[9];
    const float* bk2 = (const float*)d_in[10];
    const float* Wv2 = (const float*)d_in[11];
    const float* bv2 = (const float*)d_in[12];
    const float* Wc  = (const float*)d_in[13];
    const float* bc  = (const float*)d_in[14];
    const float* gam = (const float*)d_in[15];
    const float* bet = (const float*)d_in[16];
    float* out = (float*)d_out;

    float* sb = nullptr;
    cudaGetSymbolAddress((void**)&sb, g_scratch);

    // All six projections in one launch
    proj_kernel<<<dim3(16, 20, BATCH), 256>>>(x,
        Wq1, bq1, Wk1, bk1, Wv1, bv1,
        Wq2, bq2, Wk2, bk2, Wv2, bv2, sb);

    // Fused dual cross-attention (512 threads/block)
    const int attn_smem = (int)sizeof(AttnSmem);
    cudaFuncSetAttribute(flash_attn_kernel,
                         cudaFuncAttributeMaxDynamicSharedMemorySize, attn_smem);
    flash_attn_kernel<<<dim3(NN / 64, 2, BATCH), 512, attn_smem>>>();

    // Final 1x1 conv + BN(eval) + LeakyReLU fused
    outconv_kernel<<<dim3(16, 16, BATCH), 256>>>(Wc, bc, sb + OFF_CAT, out, gam, bet);
}

// round 9
// speedup vs baseline: 2.2465x; 2.2465x over previous
#include <cuda_runtime.h>
#include <math.h>
#include <stdint.h>

// ---------------------------------------------------------------------------
// Problem constants
// ---------------------------------------------------------------------------
#define BATCH 4
#define CIN   512
#define CC    256
#define CQ    32
#define NN    4096
#define COUT  512

#define QKPLANE (BATCH*CQ*NN)                  // floats per Q/K plane
#define PPLANE  ((size_t)NN*(size_t)NN)        // floats per P plane (per z)

// Static device scratch (~600 MB total)
__device__ __align__(16) float g_qk[4*QKPLANE];                    // Q1,K1,Q2,K2
__device__ __align__(16) float g_v[(size_t)2*BATCH*CC*NN];         // [branch][b][c][n] tf32-rounded
__device__ __align__(16) float g_p[(size_t)8*PPLANE];              // [z][n][m] tf32-rounded
__device__ __align__(16) float g_lpart[8*32*NN];                   // [z][ktile][n]
__device__ __align__(16) float g_cat[(size_t)BATCH*CIN*NN];

// ---------------------------------------------------------------------------
// Helpers
// ---------------------------------------------------------------------------
__device__ __forceinline__ float tf32r(float x) {
    uint32_t r;
    asm("cvt.rna.tf32.f32 %0, %1;" : "=r"(r) : "f"(x));
    return __uint_as_float(r);
}

__device__ __forceinline__ uint32_t smem_u32(const void* p) {
    uint32_t a;
    asm("{ .reg .u64 t; cvta.to.shared.u64 t, %1; cvt.u32.u64 %0, t; }" : "=r"(a) : "l"(p));
    return a;
}
__device__ __forceinline__ void cpasync16(uint32_t dst, const void* src) {
    asm volatile("cp.async.ca.shared.global [%0], [%1], 16;" :: "r"(dst), "l"(src));
}
#define CP_COMMIT()  asm volatile("cp.async.commit_group;" ::: "memory")
#define CP_WAIT(n)   asm volatile("cp.async.wait_group %0;" :: "n"(n) : "memory")

// m16n8k8 tf32 MMA (sm_80+ PTX; runs on tensor pipe)
__device__ __forceinline__ void mma_tf32(float d[4], const uint32_t a[4],
                                         uint32_t b0, uint32_t b1) {
    asm volatile("mma.sync.aligned.m16n8k8.row.col.f32.tf32.tf32.f32 "
                 "{%0,%1,%2,%3}, {%4,%5,%6,%7}, {%8,%9}, {%0,%1,%2,%3};"
                 : "+f"(d[0]), "+f"(d[1]), "+f"(d[2]), "+f"(d[3])
                 : "r"(a[0]), "r"(a[1]), "r"(a[2]), "r"(a[3]), "r"(b0), "r"(b1));
}

// Fast exp: FMA/ALU only (no MUFU). rel err ~2e-7 for |x| < 60.
__device__ __forceinline__ float fexp(float x) {
    float t = x * 1.4426950408889634f;
    float z = t + 12582912.0f;
    int   i = __float_as_int(z);
    float r = z - 12582912.0f;
    float d = t - r;
    float q = fmaf(d, 1.5403530e-4f, 1.3333558e-3f);
    q = fmaf(d, q, 9.6181291e-3f);
    q = fmaf(d, q, 5.5504109e-2f);
    q = fmaf(d, q, 2.4022651e-1f);
    q = fmaf(d, q, 6.9314718e-1f);
    q = fmaf(d, q, 1.0f);
    return __int_as_float(__float_as_int(q) + (i << 23));
}

// ---------------------------------------------------------------------------
// Scalar fp32 GEMM body (R3-proven): 32(O) x 256(N) tile
// ---------------------------------------------------------------------------
__device__ __forceinline__
void gemm_acc(const float* __restrict__ W, const float* __restrict__ Xb,
              int Kd, int o0, int n0, float acc[4][8],
              float Ws[32][32], float Xs[32][256])
{
    const int t  = threadIdx.x;
    const int tx = t & 31;
    const int ty = t >> 5;
#pragma unroll
    for (int i = 0; i < 4; i++)
#pragma unroll
        for (int j = 0; j < 8; j++) acc[i][j] = 0.f;

    for (int k0 = 0; k0 < Kd; k0 += 32) {
        {
            int l = t * 4;
            int r = l >> 5, c = l & 31;
            *(float4*)&Ws[r][c] = *(const float4*)(W + (size_t)(o0 + r) * Kd + k0 + c);
        }
#pragma unroll
        for (int u = 0; u < 8; u++) {
            int f = t + 256 * u;
            int r = f >> 6;
            int c = (f & 63) * 4;
            *(float4*)&Xs[r][c] = *(const float4*)(Xb + (size_t)(k0 + r) * NN + n0 + c);
        }
        __syncthreads();
#pragma unroll
        for (int kk = 0; kk < 32; kk++) {
            float4 xa = *(const float4*)&Xs[kk][tx * 4];
            float4 xb = *(const float4*)&Xs[kk][tx * 4 + 128];
            float wv[4];
#pragma unroll
            for (int i = 0; i < 4; i++) wv[i] = Ws[ty * 4 + i][kk];
#pragma unroll
            for (int i = 0; i < 4; i++) {
                acc[i][0] += wv[i] * xa.x; acc[i][1] += wv[i] * xa.y;
                acc[i][2] += wv[i] * xa.z; acc[i][3] += wv[i] * xa.w;
                acc[i][4] += wv[i] * xb.x; acc[i][5] += wv[i] * xb.y;
                acc[i][6] += wv[i] * xb.z; acc[i][7] += wv[i] * xb.w;
            }
        }
        __syncthreads();
    }
}

// ---------------------------------------------------------------------------
// Projections: one launch, grid (16, 20, BATCH)
//   sy 0..3  : q1,k1,q2,k2 -> fp32 planes
//   sy 4..11 : v1 o-tiles; sy 12..19: v2 o-tiles -> tf32-rounded fp32 planes
// ---------------------------------------------------------------------------
__global__ __launch_bounds__(256)
void proj_kernel(const float* __restrict__ x,
                 const float* __restrict__ Wq1, const float* __restrict__ bq1,
                 const float* __restrict__ Wk1, const float* __restrict__ bk1,
                 const float* __restrict__ Wv1, const float* __restrict__ bv1,
                 const float* __restrict__ Wq2, const float* __restrict__ bq2,
                 const float* __restrict__ Wk2, const float* __restrict__ bk2,
                 const float* __restrict__ Wv2, const float* __restrict__ bv2)
{
    __shared__ float Ws[32][32];
    __shared__ float Xs[32][256];

    const int sy = blockIdx.y;
    const int bz = blockIdx.z;
    const int n0 = blockIdx.x * 256;
    const int t  = threadIdx.x;
    const int tx = t & 31, ty = t >> 5;
    const size_t XB = (size_t)bz * CIN * NN;
    float acc[4][8];

    if (sy < 4) {
        const float *W, *bias, *Xb;
        float* Yb;
        switch (sy) {
            case 0:  W = Wq1; bias = bq1; Xb = x + XB;           Yb = g_qk + 0*QKPLANE; break;
            case 1:  W = Wk1; bias = bk1; Xb = x + XB;           Yb = g_qk + 1*QKPLANE; break;
            case 2:  W = Wq2; bias = bq2; Xb = x + XB + CC * NN; Yb = g_qk + 2*QKPLANE; break;
            default: W = Wk2; bias = bk2; Xb = x + XB + CC * NN; Yb = g_qk + 3*QKPLANE; break;
        }
        Yb += (size_t)bz * CQ * NN;
        gemm_acc(W, Xb, CC, 0, n0, acc, Ws, Xs);
#pragma unroll
        for (int i = 0; i < 4; i++) {
            int o = ty * 4 + i;
            float bv = bias[o];
            float v[8];
#pragma unroll
            for (int j = 0; j < 8; j++) v[j] = acc[i][j] + bv;
            *(float4*)(Yb + (size_t)o * NN + n0 + tx * 4)       = make_float4(v[0], v[1], v[2], v[3]);
            *(float4*)(Yb + (size_t)o * NN + n0 + tx * 4 + 128) = make_float4(v[4], v[5], v[6], v[7]);
        }
    } else {
        int vsl = sy - 4;
        int br  = vsl >> 3;
        int o0  = (vsl & 7) * 32;
        const float* W    = br ? Wv2 : Wv1;
        const float* bias = br ? bv2 : bv1;
        const float* Xb   = x + XB + (size_t)br * CC * NN;
        float* Vb = g_v + ((size_t)br * BATCH + bz) * (size_t)CC * NN;

        gemm_acc(W, Xb, CC, o0, n0, acc, Ws, Xs);
#pragma unroll
        for (int i = 0; i < 4; i++) {
            int o = o0 + ty * 4 + i;
            float bv = bias[o];
            float v[8];
#pragma unroll
            for (int j = 0; j < 8; j++) v[j] = tf32r(acc[i][j] + bv);
            *(float4*)(Vb + (size_t)o * NN + n0 + tx * 4)       = make_float4(v[0], v[1], v[2], v[3]);
            *(float4*)(Vb + (size_t)o * NN + n0 + tx * 4 + 128) = make_float4(v[4], v[5], v[6], v[7]);
        }
    }
}

// ---------------------------------------------------------------------------
// QK + exp + tf32-rounded P + deterministic row-sum partials
// grid (32 ktiles, 64 qtiles, 8 z), 256 threads. Tile: 64 q x 128 keys.
// ---------------------------------------------------------------------------
__global__ __launch_bounds__(256)
void qk_exp_kernel()
{
    __shared__ float Qs[32][64];
    __shared__ float Ks[32][128];

    const int t  = threadIdx.x;
    const int kx = blockIdx.x;
    const int qy = blockIdx.y;
    const int z  = blockIdx.z;   // b*2 + a
    const int b  = z >> 1, a = z & 1;

    const float* Q = g_qk + (a == 0 ? 2 : 0) * QKPLANE + (size_t)b * CQ * NN;
    const float* K = g_qk + (a == 0 ? 1 : 3) * QKPLANE + (size_t)b * CQ * NN;
    const int n0 = qy * 64, m0 = kx * 128;

#pragma unroll
    for (int it = 0; it < 2; it++) {
        int f = t + 256 * it;
        int d = f >> 4, c = (f & 15) * 4;
        *(float4*)&Qs[d][c] = *(const float4*)(Q + (size_t)d * NN + n0 + c);
    }
#pragma unroll
    for (int it = 0; it < 4; it++) {
        int f = t + 256 * it;
        int d = f >> 5, c = (f & 31) * 4;
        *(float4*)&Ks[d][c] = *(const float4*)(K + (size_t)d * NN + m0 + c);
    }
    __syncthreads();

    const int ig = t >> 4;   // 0..15 -> 4 query rows each
    const int jg = t & 15;   // 0..15 -> 8 key cols each

    float acc[4][8];
#pragma unroll
    for (int r = 0; r < 4; r++)
#pragma unroll
        for (int c = 0; c < 8; c++) acc[r][c] = 0.f;

#pragma unroll
    for (int d = 0; d < 32; d++) {
        float4 q4 = *(const float4*)&Qs[d][ig * 4];
        float4 ka = *(const float4*)&Ks[d][jg * 8];
        float4 kb = *(const float4*)&Ks[d][jg * 8 + 4];
        float qv[4] = {q4.x, q4.y, q4.z, q4.w};
#pragma unroll
        for (int r = 0; r < 4; r++) {
            acc[r][0] += qv[r] * ka.x; acc[r][1] += qv[r] * ka.y;
            acc[r][2] += qv[r] * ka.z; acc[r][3] += qv[r] * ka.w;
            acc[r][4] += qv[r] * kb.x; acc[r][5] += qv[r] * kb.y;
            acc[r][6] += qv[r] * kb.z; acc[r][7] += qv[r] * kb.w;
        }
    }

    float* P = g_p + (size_t)z * PPLANE;

#pragma unroll
    for (int r = 0; r < 4; r++) {
        float p[8];
        float sum = 0.f;
#pragma unroll
        for (int c = 0; c < 8; c++) {
            p[c] = tf32r(fexp(acc[r][c]));   // round BEFORE summing (consistency)
            sum += p[c];
        }
#pragma unroll
        for (int m = 1; m < 16; m <<= 1)
            sum += __shfl_xor_sync(0xffffffffu, sum, m);
        int row = n0 + ig * 4 + r;
        if (jg == 0)
            g_lpart[((size_t)z * 32 + kx) * NN + row] = sum;

        float* dst = P + (size_t)row * NN + m0 + jg * 8;
        *(float4*)(dst)     = make_float4(p[0], p[1], p[2], p[3]);
        *(float4*)(dst + 4) = make_float4(p[4], p[5], p[6], p[7]);
    }
}

// ---------------------------------------------------------------------------
// PV via mma.sync tf32 (tensor path, legal at sm_100).
// CTA: 128q x 128c, 8 warps (4q x 2c), warp tile 32q x 64c.
// K in 32-chunks, double-buffered cp.async. smem pitch 36 -> conflict-free.
// grid (32 qb, 2 ch, 8 z), 256 threads, dyn smem 73728 B.
// ---------------------------------------------------------------------------
#define PVPITCH 36
#define PVBUF   (128 * PVPITCH)            // floats per (P or V) buffer
extern __shared__ float pv_sm[];           // [2][PVBUF] P then [2][PVBUF] V

__global__ __launch_bounds__(256)
void pv_mma_kernel()
{
    const int t    = threadIdx.x;
    const int lane = t & 31;
    const int warp = t >> 5;
    const int wq   = warp & 3;          // 0..3  (q-group of 32)
    const int wc   = warp >> 2;         // 0..1  (c-group of 64)
    const int qb   = blockIdx.x;
    const int ch   = blockIdx.y;
    const int z    = blockIdx.z;
    const int b    = z >> 1, a = z & 1;
    const int n0   = qb * 128;
    const int c0   = ch * 128;

    const float* P = g_p + (size_t)z * PPLANE + (size_t)n0 * NN;
    const float* V = g_v + ((size_t)a * BATCH + b) * (size_t)CC * NN + (size_t)c0 * NN;

    float* Pb[2] = { pv_sm,              pv_sm + PVBUF };
    float* Vb[2] = { pv_sm + 2 * PVBUF,  pv_sm + 3 * PVBUF };
    const uint32_t sm0 = smem_u32(pv_sm);

    // async-load one 32-wide K chunk into buffer `buf`
    auto load_chunk = [&](int buf, int kc) {
        const int m0 = kc * 32;
        const uint32_t pd = sm0 + (uint32_t)(buf * PVBUF) * 4;
        const uint32_t vd = sm0 + (uint32_t)((2 + buf) * PVBUF) * 4;
#pragma unroll
        for (int i = 0; i < 4; i++) {
            int f = t + 256 * i;
            int row = f >> 3, c4 = f & 7;
            cpasync16(pd + (uint32_t)(row * PVPITCH + c4 * 4) * 4,
                      P + (size_t)row * NN + m0 + c4 * 4);
            cpasync16(vd + (uint32_t)(row * PVPITCH + c4 * 4) * 4,
                      V + (size_t)row * NN + m0 + c4 * 4);
        }
        CP_COMMIT();
    };

    float acc[2][8][4];
#pragma unroll
    for (int mt = 0; mt < 2; mt++)
#pragma unroll
        for (int nt = 0; nt < 8; nt++)
#pragma unroll
            for (int e = 0; e < 4; e++) acc[mt][nt][e] = 0.f;

    const int r4 = lane >> 2;
    const int c4 = lane & 3;

    load_chunk(0, 0);
    for (int kc = 0; kc < 128; kc++) {
        const int buf = kc & 1;
        if (kc < 127) load_chunk(buf ^ 1, kc + 1);
        if (kc < 127) { CP_WAIT(1); } else { CP_WAIT(0); }
        __syncthreads();

        const float* Ps = Pb[buf];
        const float* Vs = Vb[buf];
#pragma unroll
        for (int ks = 0; ks < 4; ks++) {
            const int kcol = ks * 8 + c4;
            uint32_t A[2][4];
#pragma unroll
            for (int mt = 0; mt < 2; mt++) {
                const int rb = wq * 32 + mt * 16;
                A[mt][0] = __float_as_uint(Ps[(rb + r4)     * PVPITCH + kcol]);
                A[mt][1] = __float_as_uint(Ps[(rb + r4 + 8) * PVPITCH + kcol]);
                A[mt][2] = __float_as_uint(Ps[(rb + r4)     * PVPITCH + kcol + 4]);
                A[mt][3] = __float_as_uint(Ps[(rb + r4 + 8) * PVPITCH + kcol + 4]);
            }
#pragma unroll
            for (int nt = 0; nt < 8; nt++) {
                const int cb = wc * 64 + nt * 8;
                uint32_t B0 = __float_as_uint(Vs[(cb + r4) * PVPITCH + kcol]);
                uint32_t B1 = __float_as_uint(Vs[(cb + r4) * PVPITCH + kcol + 4]);
                mma_tf32(acc[0][nt], A[0], B0, B1);
                mma_tf32(acc[1][nt], A[1], B0, B1);
            }
        }
        __syncthreads();
    }

    // row-sum normalizers for this CTA's 128 q rows
    float* lrow = pv_sm;   // reuse buffer 0
    if (t < 128) {
        float s = 0.f;
#pragma unroll
        for (int x = 0; x < 32; x++)
            s += g_lpart[((size_t)z * 32 + x) * NN + n0 + t];
        lrow[t] = 1.f / s;
    }
    __syncthreads();

    // writeout: D[q][c] -> g_cat[c_global][n0+q]
#pragma unroll
    for (int mt = 0; mt < 2; mt++) {
        const int q0l = wq * 32 + mt * 16 + r4;
        float li0 = lrow[q0l];
        float li1 = lrow[q0l + 8];
#pragma unroll
        for (int nt = 0; nt < 8; nt++) {
            const int cb = wc * 64 + nt * 8 + 2 * c4;
#pragma unroll
            for (int e = 0; e < 4; e++) {
                const int ql = (e >= 2) ? q0l + 8 : q0l;
                const float li = (e >= 2) ? li1 : li0;
                const int cl = cb + (e & 1);
                g_cat[((size_t)b * CIN + a * 256 + c0 + cl) * NN + n0 + ql] =
                    acc[mt][nt][e] * li;
            }
        }
    }
}

// ---------------------------------------------------------------------------
// Final 1x1 conv (K=512) + BN(eval) + LeakyReLU fused
// ---------------------------------------------------------------------------
__global__ __launch_bounds__(256)
void outconv_kernel(const float* __restrict__ W, const float* __restrict__ bias,
                    float* __restrict__ Y,
                    const float* __restrict__ gamma, const float* __restrict__ beta)
{
    __shared__ float Ws[32][32];
    __shared__ float Xs[32][256];

    const int n0 = blockIdx.x * 256;
    const int o0 = blockIdx.y * 32;
    const int t  = threadIdx.x;
    const int tx = t & 31, ty = t >> 5;
    const float* Xb = g_cat + (size_t)blockIdx.z * CIN * NN;
    float*       Yb = Y + (size_t)blockIdx.z * COUT * NN;

    float acc[4][8];
    gemm_acc(W, Xb, CIN, o0, n0, acc, Ws, Xs);

    const float inv_bn = rsqrtf(1.0f + 1e-5f);
#pragma unroll
    for (int i = 0; i < 4; i++) {
        int o = o0 + ty * 4 + i;
        float bv = bias[o];
        float g = gamma[o] * inv_bn, be = beta[o];
        float v[8];
#pragma unroll
        for (int j = 0; j < 8; j++) {
            float y = acc[i][j] + bv;
            y = y * g + be;
            v[j] = (y > 0.f) ? y : 0.2f * y;
        }
        *(float4*)(Yb + (size_t)o * NN + n0 + tx * 4)       = make_float4(v[0], v[1], v[2], v[3]);
        *(float4*)(Yb + (size_t)o * NN + n0 + tx * 4 + 128) = make_float4(v[4], v[5], v[6], v[7]);
    }
}

// ---------------------------------------------------------------------------
// Launch
// ---------------------------------------------------------------------------
extern "C" void kernel_launch(void* const* d_in, const int* in_sizes, int n_in,
                              void* d_out, int out_size)
{
    const float* x   = (const float*)d_in[0];
    const float* Wq1 = (const float*)d_in[1];
    const float* bq1 = (const float*)d_in[2];
    const float* Wk1 = (const float*)d_in[3];
    const float* bk1 = (const float*)d_in[4];
    const float* Wv1 = (const float*)d_in[5];
    const float* bv1 = (const float*)d_in[6];
    const float* Wq2 = (const float*)d_in[7];
    const float* bq2 = (const float*)d_in[8];
    const float* Wk2 = (const float*)d_in[9];
    const float* bk2 = (const float*)d_in[10];
    const float* Wv2 = (const float*)d_in[11];
    const float* bv2 = (const float*)d_in[12];
    const float* Wc  = (const float*)d_in[13];
    const float* bc  = (const float*)d_in[14];
    const float* gam = (const float*)d_in[15];
    const float* bet = (const float*)d_in[16];
    float* out = (float*)d_out;

    proj_kernel<<<dim3(16, 20, BATCH), 256>>>(x,
        Wq1, bq1, Wk1, bk1, Wv1, bv1,
        Wq2, bq2, Wk2, bk2, Wv2, bv2);

    qk_exp_kernel<<<dim3(32, 64, 8), 256>>>();

    const int pv_smem = 4 * PVBUF * (int)sizeof(float);   // 73728 B
    cudaFuncSetAttribute(pv_mma_kernel,
                         cudaFuncAttributeMaxDynamicSharedMemorySize, pv_smem);
    pv_mma_kernel<<<dim3(32, 2, 8), 256, pv_smem>>>();

    outconv_kernel<<<dim3(16, 16, BATCH), 256>>>(Wc, bc, out, gam, bet);
}

// round 10
// speedup vs baseline: 2.8092x; 1.2505x over previous
#include <cuda_runtime.h>
#include <math.h>
#include <stdint.h>

// ---------------------------------------------------------------------------
// Problem constants
// ---------------------------------------------------------------------------
#define BATCH 4
#define CIN   512
#define CC    256
#define CQ    32
#define NN    4096
#define COUT  512

#define QKPLANE (BATCH*CQ*NN)                  // floats per Q/K plane
#define PPLANE  ((size_t)NN*(size_t)NN)        // floats per P plane (per z)

// Static device scratch (~600 MB total)
__device__ __align__(16) float g_qk[4*QKPLANE];                    // Q1,K1,Q2,K2
__device__ __align__(16) float g_v[(size_t)2*BATCH*CC*NN];         // [branch][b][c][n] tf32-rounded
__device__ __align__(16) float g_p[(size_t)8*PPLANE];              // [z][n][m] tf32-rounded
__device__ __align__(16) float g_lpart[8*32*NN];                   // [z][ktile][n]
__device__ __align__(16) float g_cat[(size_t)BATCH*CIN*NN];        // tf32-rounded
__device__ __align__(16) float g_wt[COUT*CIN];                     // Wc tf32-rounded

// ---------------------------------------------------------------------------
// Helpers
// ---------------------------------------------------------------------------
__device__ __forceinline__ float tf32r(float x) {
    uint32_t r;
    asm("cvt.rna.tf32.f32 %0, %1;" : "=r"(r) : "f"(x));
    return __uint_as_float(r);
}

__device__ __forceinline__ uint32_t smem_u32(const void* p) {
    uint32_t a;
    asm("{ .reg .u64 t; cvta.to.shared.u64 t, %1; cvt.u32.u64 %0, t; }" : "=r"(a) : "l"(p));
    return a;
}
__device__ __forceinline__ void cpasync16(uint32_t dst, const void* src) {
    asm volatile("cp.async.ca.shared.global [%0], [%1], 16;" :: "r"(dst), "l"(src));
}
#define CP_COMMIT()  asm volatile("cp.async.commit_group;" ::: "memory")
#define CP_WAIT(n)   asm volatile("cp.async.wait_group %0;" :: "n"(n) : "memory")

// m16n8k8 tf32 MMA (sm_80+ PTX; tensor pipe)
__device__ __forceinline__ void mma_tf32(float d[4], const uint32_t a[4],
                                         uint32_t b0, uint32_t b1) {
    asm volatile("mma.sync.aligned.m16n8k8.row.col.f32.tf32.tf32.f32 "
                 "{%0,%1,%2,%3}, {%4,%5,%6,%7}, {%8,%9}, {%0,%1,%2,%3};"
                 : "+f"(d[0]), "+f"(d[1]), "+f"(d[2]), "+f"(d[3])
                 : "r"(a[0]), "r"(a[1]), "r"(a[2]), "r"(a[3]), "r"(b0), "r"(b1));
}

// Fast exp: FMA/ALU only (no MUFU). rel err ~2e-7 for |x| < 60.
__device__ __forceinline__ float fexp(float x) {
    float t = x * 1.4426950408889634f;
    float z = t + 12582912.0f;
    int   i = __float_as_int(z);
    float r = z - 12582912.0f;
    float d = t - r;
    float q = fmaf(d, 1.5403530e-4f, 1.3333558e-3f);
    q = fmaf(d, q, 9.6181291e-3f);
    q = fmaf(d, q, 5.5504109e-2f);
    q = fmaf(d, q, 2.4022651e-1f);
    q = fmaf(d, q, 6.9314718e-1f);
    q = fmaf(d, q, 1.0f);
    return __int_as_float(__float_as_int(q) + (i << 23));
}

// ---------------------------------------------------------------------------
// Scalar fp32 GEMM body (proj only): 32(O) x 256(N) tile
// ---------------------------------------------------------------------------
__device__ __forceinline__
void gemm_acc(const float* __restrict__ W, const float* __restrict__ Xb,
              int Kd, int o0, int n0, float acc[4][8],
              float Ws[32][32], float Xs[32][256])
{
    const int t  = threadIdx.x;
    const int tx = t & 31;
    const int ty = t >> 5;
#pragma unroll
    for (int i = 0; i < 4; i++)
#pragma unroll
        for (int j = 0; j < 8; j++) acc[i][j] = 0.f;

    for (int k0 = 0; k0 < Kd; k0 += 32) {
        {
            int l = t * 4;
            int r = l >> 5, c = l & 31;
            *(float4*)&Ws[r][c] = *(const float4*)(W + (size_t)(o0 + r) * Kd + k0 + c);
        }
#pragma unroll
        for (int u = 0; u < 8; u++) {
            int f = t + 256 * u;
            int r = f >> 6;
            int c = (f & 63) * 4;
            *(float4*)&Xs[r][c] = *(const float4*)(Xb + (size_t)(k0 + r) * NN + n0 + c);
        }
        __syncthreads();
#pragma unroll
        for (int kk = 0; kk < 32; kk++) {
            float4 xa = *(const float4*)&Xs[kk][tx * 4];
            float4 xb = *(const float4*)&Xs[kk][tx * 4 + 128];
            float wv[4];
#pragma unroll
            for (int i = 0; i < 4; i++) wv[i] = Ws[ty * 4 + i][kk];
#pragma unroll
            for (int i = 0; i < 4; i++) {
                acc[i][0] += wv[i] * xa.x; acc[i][1] += wv[i] * xa.y;
                acc[i][2] += wv[i] * xa.z; acc[i][3] += wv[i] * xa.w;
                acc[i][4] += wv[i] * xb.x; acc[i][5] += wv[i] * xb.y;
                acc[i][6] += wv[i] * xb.z; acc[i][7] += wv[i] * xb.w;
            }
        }
        __syncthreads();
    }
}

// ---------------------------------------------------------------------------
// Projections: one launch, grid (16, 20, BATCH)
// ---------------------------------------------------------------------------
__global__ __launch_bounds__(256)
void proj_kernel(const float* __restrict__ x,
                 const float* __restrict__ Wq1, const float* __restrict__ bq1,
                 const float* __restrict__ Wk1, const float* __restrict__ bk1,
                 const float* __restrict__ Wv1, const float* __restrict__ bv1,
                 const float* __restrict__ Wq2, const float* __restrict__ bq2,
                 const float* __restrict__ Wk2, const float* __restrict__ bk2,
                 const float* __restrict__ Wv2, const float* __restrict__ bv2)
{
    __shared__ float Ws[32][32];
    __shared__ float Xs[32][256];

    const int sy = blockIdx.y;
    const int bz = blockIdx.z;
    const int n0 = blockIdx.x * 256;
    const int t  = threadIdx.x;
    const int tx = t & 31, ty = t >> 5;
    const size_t XB = (size_t)bz * CIN * NN;
    float acc[4][8];

    if (sy < 4) {
        const float *W, *bias, *Xb;
        float* Yb;
        switch (sy) {
            case 0:  W = Wq1; bias = bq1; Xb = x + XB;           Yb = g_qk + 0*QKPLANE; break;
            case 1:  W = Wk1; bias = bk1; Xb = x + XB;           Yb = g_qk + 1*QKPLANE; break;
            case 2:  W = Wq2; bias = bq2; Xb = x + XB + CC * NN; Yb = g_qk + 2*QKPLANE; break;
            default: W = Wk2; bias = bk2; Xb = x + XB + CC * NN; Yb = g_qk + 3*QKPLANE; break;
        }
        Yb += (size_t)bz * CQ * NN;
        gemm_acc(W, Xb, CC, 0, n0, acc, Ws, Xs);
#pragma unroll
        for (int i = 0; i < 4; i++) {
            int o = ty * 4 + i;
            float bv = bias[o];
            float v[8];
#pragma unroll
            for (int j = 0; j < 8; j++) v[j] = acc[i][j] + bv;
            *(float4*)(Yb + (size_t)o * NN + n0 + tx * 4)       = make_float4(v[0], v[1], v[2], v[3]);
            *(float4*)(Yb + (size_t)o * NN + n0 + tx * 4 + 128) = make_float4(v[4], v[5], v[6], v[7]);
        }
    } else {
        int vsl = sy - 4;
        int br  = vsl >> 3;
        int o0  = (vsl & 7) * 32;
        const float* W    = br ? Wv2 : Wv1;
        const float* bias = br ? bv2 : bv1;
        const float* Xb   = x + XB + (size_t)br * CC * NN;
        float* Vb = g_v + ((size_t)br * BATCH + bz) * (size_t)CC * NN;

        gemm_acc(W, Xb, CC, o0, n0, acc, Ws, Xs);
#pragma unroll
        for (int i = 0; i < 4; i++) {
            int o = o0 + ty * 4 + i;
            float bv = bias[o];
            float v[8];
#pragma unroll
            for (int j = 0; j < 8; j++) v[j] = tf32r(acc[i][j] + bv);
            *(float4*)(Vb + (size_t)o * NN + n0 + tx * 4)       = make_float4(v[0], v[1], v[2], v[3]);
            *(float4*)(Vb + (size_t)o * NN + n0 + tx * 4 + 128) = make_float4(v[4], v[5], v[6], v[7]);
        }
    }
}

// ---------------------------------------------------------------------------
// QK + exp + tf32-rounded P + deterministic row-sum partials
// ---------------------------------------------------------------------------
__global__ __launch_bounds__(256)
void qk_exp_kernel()
{
    __shared__ float Qs[32][64];
    __shared__ float Ks[32][128];

    const int t  = threadIdx.x;
    const int kx = blockIdx.x;
    const int qy = blockIdx.y;
    const int z  = blockIdx.z;   // b*2 + a
    const int b  = z >> 1, a = z & 1;

    const float* Q = g_qk + (a == 0 ? 2 : 0) * QKPLANE + (size_t)b * CQ * NN;
    const float* K = g_qk + (a == 0 ? 1 : 3) * QKPLANE + (size_t)b * CQ * NN;
    const int n0 = qy * 64, m0 = kx * 128;

#pragma unroll
    for (int it = 0; it < 2; it++) {
        int f = t + 256 * it;
        int d = f >> 4, c = (f & 15) * 4;
        *(float4*)&Qs[d][c] = *(const float4*)(Q + (size_t)d * NN + n0 + c);
    }
#pragma unroll
    for (int it = 0; it < 4; it++) {
        int f = t + 256 * it;
        int d = f >> 5, c = (f & 31) * 4;
        *(float4*)&Ks[d][c] = *(const float4*)(K + (size_t)d * NN + m0 + c);
    }
    __syncthreads();

    const int ig = t >> 4;
    const int jg = t & 15;

    float acc[4][8];
#pragma unroll
    for (int r = 0; r < 4; r++)
#pragma unroll
        for (int c = 0; c < 8; c++) acc[r][c] = 0.f;

#pragma unroll
    for (int d = 0; d < 32; d++) {
        float4 q4 = *(const float4*)&Qs[d][ig * 4];
        float4 ka = *(const float4*)&Ks[d][jg * 8];
        float4 kb = *(const float4*)&Ks[d][jg * 8 + 4];
        float qv[4] = {q4.x, q4.y, q4.z, q4.w};
#pragma unroll
        for (int r = 0; r < 4; r++) {
            acc[r][0] += qv[r] * ka.x; acc[r][1] += qv[r] * ka.y;
            acc[r][2] += qv[r] * ka.z; acc[r][3] += qv[r] * ka.w;
            acc[r][4] += qv[r] * kb.x; acc[r][5] += qv[r] * kb.y;
            acc[r][6] += qv[r] * kb.z; acc[r][7] += qv[r] * kb.w;
        }
    }

    float* P = g_p + (size_t)z * PPLANE;

#pragma unroll
    for (int r = 0; r < 4; r++) {
        float p[8];
        float sum = 0.f;
#pragma unroll
        for (int c = 0; c < 8; c++) {
            p[c] = tf32r(fexp(acc[r][c]));   // round BEFORE summing
            sum += p[c];
        }
#pragma unroll
        for (int m = 1; m < 16; m <<= 1)
            sum += __shfl_xor_sync(0xffffffffu, sum, m);
        int row = n0 + ig * 4 + r;
        if (jg == 0)
            g_lpart[((size_t)z * 32 + kx) * NN + row] = sum;

        float* dst = P + (size_t)row * NN + m0 + jg * 8;
        *(float4*)(dst)     = make_float4(p[0], p[1], p[2], p[3]);
        *(float4*)(dst + 4) = make_float4(p[4], p[5], p[6], p[7]);
    }
}

// ---------------------------------------------------------------------------
// PV via mma.sync tf32. CTA: 128q x 256c (full C => P read ONCE).
// 8 warps (wq 0..3 x wc 0..1), warp tile 32q x 128c, acc 2x16x4.
// K in 32-chunks, double-buffered cp.async. Staged coalesced writeout.
// grid (32 qb, 8 z), 256 threads, dyn smem 110592 B.
// ---------------------------------------------------------------------------
#define PV_A0 0
#define PV_A1 (128*36)                 // 4608
#define PV_B0 (2*128*36)               // 9216
#define PV_B1 (PV_B0 + 256*36)         // 18432
#define PV_SMEM_FLOATS (PV_B1 + 256*36)   // 27648 floats = 110592 B
extern __shared__ float pv_sm[];

__global__ __launch_bounds__(256)
void pv_mma_kernel()
{
    const int t    = threadIdx.x;
    const int lane = t & 31;
    const int warp = t >> 5;
    const int wq   = warp & 3;          // q-group of 32
    const int wc   = warp >> 2;         // c-half (0..1) of 128
    const int qb   = blockIdx.x;
    const int z    = blockIdx.y;
    const int b    = z >> 1, a = z & 1;
    const int n0   = qb * 128;

    const float* P = g_p + (size_t)z * PPLANE + (size_t)n0 * NN;
    const float* V = g_v + ((size_t)a * BATCH + b) * (size_t)CC * NN;
    const uint32_t sm0 = smem_u32(pv_sm);

    auto load_chunk = [&](int buf, int kc) {
        const int m0 = kc * 32;
        const uint32_t pd = sm0 + (uint32_t)(buf ? PV_A1 : PV_A0) * 4;
        const uint32_t vd = sm0 + (uint32_t)(buf ? PV_B1 : PV_B0) * 4;
#pragma unroll
        for (int i = 0; i < 4; i++) {           // P: 128 rows x 32 k
            int f = t + 256 * i;
            int row = f >> 3, c4 = f & 7;
            cpasync16(pd + (uint32_t)(row * 36 + c4 * 4) * 4,
                      P + (size_t)row * NN + m0 + c4 * 4);
        }
#pragma unroll
        for (int i = 0; i < 8; i++) {           // V: 256 rows x 32 k
            int f = t + 256 * i;
            int row = f >> 3, c4 = f & 7;
            cpasync16(vd + (uint32_t)(row * 36 + c4 * 4) * 4,
                      V + (size_t)row * NN + m0 + c4 * 4);
        }
        CP_COMMIT();
    };

    float acc[2][16][4];
#pragma unroll
    for (int mt = 0; mt < 2; mt++)
#pragma unroll
        for (int nt = 0; nt < 16; nt++)
#pragma unroll
            for (int e = 0; e < 4; e++) acc[mt][nt][e] = 0.f;

    const int r4 = lane >> 2;
    const int c4 = lane & 3;

    load_chunk(0, 0);
    for (int kc = 0; kc < 128; kc++) {
        const int buf = kc & 1;
        if (kc < 127) load_chunk(buf ^ 1, kc + 1);
        if (kc < 127) { CP_WAIT(1); } else { CP_WAIT(0); }
        __syncthreads();

        const float* Ps = pv_sm + (buf ? PV_A1 : PV_A0);
        const float* Vs = pv_sm + (buf ? PV_B1 : PV_B0);
#pragma unroll
        for (int ks = 0; ks < 4; ks++) {
            const int kcol = ks * 8 + c4;
            uint32_t A[2][4];
#pragma unroll
            for (int mt = 0; mt < 2; mt++) {
                const int rb = wq * 32 + mt * 16;
                A[mt][0] = __float_as_uint(Ps[(rb + r4)     * 36 + kcol]);
                A[mt][1] = __float_as_uint(Ps[(rb + r4 + 8) * 36 + kcol]);
                A[mt][2] = __float_as_uint(Ps[(rb + r4)     * 36 + kcol + 4]);
                A[mt][3] = __float_as_uint(Ps[(rb + r4 + 8) * 36 + kcol + 4]);
            }
#pragma unroll
            for (int nt = 0; nt < 16; nt++) {
                const int cb = wc * 128 + nt * 8;
                uint32_t B0 = __float_as_uint(Vs[(cb + r4) * 36 + kcol]);
                uint32_t B1 = __float_as_uint(Vs[(cb + r4) * 36 + kcol + 4]);
                mma_tf32(acc[0][nt], A[0], B0, B1);
                mma_tf32(acc[1][nt], A[1], B0, B1);
            }
        }
        __syncthreads();
    }

    // row-sum normalizers (deterministic) -> pv_sm[0..127] (A region, now free)
    if (t < 128) {
        float s = 0.f;
#pragma unroll
        for (int x = 0; x < 32; x++)
            s += g_lpart[((size_t)z * 32 + x) * NN + n0 + t];
        pv_sm[t] = 1.f / s;
    }
    __syncthreads();

    // staged coalesced writeout, two c-halves through B region
    float* stage = pv_sm + PV_B0;      // 128 x pitch-132 floats
    const int rowc = t >> 1;
    const int q0c  = (t & 1) * 64;
    for (int h = 0; h < 2; h++) {
        if (wc == h) {
#pragma unroll
            for (int mt = 0; mt < 2; mt++)
#pragma unroll
                for (int nt = 0; nt < 16; nt++)
#pragma unroll
                    for (int e = 0; e < 4; e++) {
                        int ql = wq * 32 + mt * 16 + r4 + ((e >= 2) ? 8 : 0);
                        int cl = nt * 8 + 2 * c4 + (e & 1);
                        stage[cl * 132 + ql] = tf32r(acc[mt][nt][e] * pv_sm[ql]);
                    }
        }
        __syncthreads();
        {
            float* dst = g_cat + ((size_t)b * CIN + a * 256 + h * 128 + rowc) * NN + n0 + q0c;
            const float* src = stage + rowc * 132 + q0c;
#pragma unroll
            for (int u = 0; u < 16; u++)
                *(float4*)(dst + u * 4) = *(const float4*)(src + u * 4);
        }
        __syncthreads();
    }
}

// ---------------------------------------------------------------------------
// Round Wc to tf32 (rna) into g_wt. 256 blocks x 256 threads x 1 float4.
// ---------------------------------------------------------------------------
__global__ __launch_bounds__(256)
void round_w_kernel(const float* __restrict__ W)
{
    int i = blockIdx.x * 256 + threadIdx.x;
    float4 v = ((const float4*)W)[i];
    v.x = tf32r(v.x); v.y = tf32r(v.y); v.z = tf32r(v.z); v.w = tf32r(v.w);
    ((float4*)g_wt)[i] = v;
}

// ---------------------------------------------------------------------------
// Final 1x1 conv on tf32 mma + BN(eval) + LeakyReLU fused.
// CTA 128o x 128n, K=512 in 16 chunks double-buffered.
// grid (32 nb, 4 ob, BATCH), 256 threads, dyn smem 71680 B.
// ---------------------------------------------------------------------------
#define OC_A0 0
#define OC_A1 (128*36)                 // 4608
#define OC_B0 (2*128*36)               // 9216
#define OC_B1 (OC_B0 + 32*136)         // 13568
#define OC_SMEM_FLOATS (OC_B1 + 32*136)   // 17920 floats = 71680 B
extern __shared__ float oc_sm[];

__global__ __launch_bounds__(256)
void outconv_mma_kernel(const float* __restrict__ bias, float* __restrict__ Y,
                        const float* __restrict__ gamma, const float* __restrict__ beta)
{
    const int t    = threadIdx.x;
    const int lane = t & 31;
    const int warp = t >> 5;
    const int wq   = warp & 3;          // o-group of 32
    const int wc   = warp >> 2;         // n-half (0..1) of 64
    const int nb0  = blockIdx.x * 128;
    const int o0   = blockIdx.y * 128;
    const int b    = blockIdx.z;

    const float* Wt = g_wt + (size_t)o0 * CIN;
    const float* X  = g_cat + (size_t)b * CIN * NN;
    float* Yb = Y + (size_t)b * COUT * NN;
    const uint32_t sm0 = smem_u32(oc_sm);

    auto load_chunk = [&](int buf, int kc) {
        const int k0 = kc * 32;
        const uint32_t ad = sm0 + (uint32_t)(buf ? OC_A1 : OC_A0) * 4;
        const uint32_t bd = sm0 + (uint32_t)(buf ? OC_B1 : OC_B0) * 4;
#pragma unroll
        for (int i = 0; i < 4; i++) {           // W: 128 rows x 32 k, pitch 36
            int f = t + 256 * i;
            int row = f >> 3, c4 = f & 7;
            cpasync16(ad + (uint32_t)(row * 36 + c4 * 4) * 4,
                      Wt + (size_t)row * CIN + k0 + c4 * 4);
        }
#pragma unroll
        for (int i = 0; i < 4; i++) {           // X: 32 rows x 128 n, pitch 136
            int f = t + 256 * i;
            int row = f >> 5, c4 = f & 31;
            cpasync16(bd + (uint32_t)(row * 136 + c4 * 4) * 4,
                      X + (size_t)(k0 + row) * NN + nb0 + c4 * 4);
        }
        CP_COMMIT();
    };

    float acc[2][8][4];
#pragma unroll
    for (int mt = 0; mt < 2; mt++)
#pragma unroll
        for (int nt = 0; nt < 8; nt++)
#pragma unroll
            for (int e = 0; e < 4; e++) acc[mt][nt][e] = 0.f;

    const int r4 = lane >> 2;
    const int c4 = lane & 3;

    load_chunk(0, 0);
    for (int kc = 0; kc < 16; kc++) {
        const int buf = kc & 1;
        if (kc < 15) load_chunk(buf ^ 1, kc + 1);
        if (kc < 15) { CP_WAIT(1); } else { CP_WAIT(0); }
        __syncthreads();

        const float* As = oc_sm + (buf ? OC_A1 : OC_A0);
        const float* Bs = oc_sm + (buf ? OC_B1 : OC_B0);
#pragma unroll
        for (int ks = 0; ks < 4; ks++) {
            const int kcol = ks * 8 + c4;
            uint32_t A[2][4];
#pragma unroll
            for (int mt = 0; mt < 2; mt++) {
                const int rb = wq * 32 + mt * 16;
                A[mt][0] = __float_as_uint(As[(rb + r4)     * 36 + kcol]);
                A[mt][1] = __float_as_uint(As[(rb + r4 + 8) * 36 + kcol]);
                A[mt][2] = __float_as_uint(As[(rb + r4)     * 36 + kcol + 4]);
                A[mt][3] = __float_as_uint(As[(rb + r4 + 8) * 36 + kcol + 4]);
            }
#pragma unroll
            for (int nt = 0; nt < 8; nt++) {
                const int nb = wc * 64 + nt * 8;
                uint32_t B0 = __float_as_uint(Bs[kcol * 136 + nb + r4]);
                uint32_t B1 = __float_as_uint(Bs[(kcol + 4) * 136 + nb + r4]);
                mma_tf32(acc[0][nt], A[0], B0, B1);
                mma_tf32(acc[1][nt], A[1], B0, B1);
            }
        }
        __syncthreads();
    }

    // stage raw accumulators (o_local x n_local, pitch 132), then fused epilogue
    float* stage = oc_sm;   // 128*132 = 16896 floats <= 17920
#pragma unroll
    for (int mt = 0; mt < 2; mt++)
#pragma unroll
        for (int nt = 0; nt < 8; nt++)
#pragma unroll
            for (int e = 0; e < 4; e++) {
                int ol = wq * 32 + mt * 16 + r4 + ((e >= 2) ? 8 : 0);
                int nl = wc * 64 + nt * 8 + 2 * c4 + (e & 1);
                stage[ol * 132 + nl] = acc[mt][nt][e];
            }
    __syncthreads();

    const float inv_bn = rsqrtf(1.0f + 1e-5f);
    {
        const int ol = t >> 1;
        const int o  = o0 + ol;
        const int nc = (t & 1) * 64;
        const float bv = bias[o];
        const float g  = gamma[o] * inv_bn;
        const float be = beta[o];
        float* dst = Yb + (size_t)o * NN + nb0 + nc;
        const float* src = stage + ol * 132 + nc;
#pragma unroll
        for (int u = 0; u < 16; u++) {
            float4 v = *(const float4*)(src + u * 4);
            float w[4] = {v.x, v.y, v.z, v.w};
#pragma unroll
            for (int q = 0; q < 4; q++) {
                float y = w[q] + bv;
                y = y * g + be;
                w[q] = (y > 0.f) ? y : 0.2f * y;
            }
            *(float4*)(dst + u * 4) = make_float4(w[0], w[1], w[2], w[3]);
        }
    }
}

// ---------------------------------------------------------------------------
// Launch
// ---------------------------------------------------------------------------
extern "C" void kernel_launch(void* const* d_in, const int* in_sizes, int n_in,
                              void* d_out, int out_size)
{
    const float* x   = (const float*)d_in[0];
    const float* Wq1 = (const float*)d_in[1];
    const float* bq1 = (const float*)d_in[2];
    const float* Wk1 = (const float*)d_in[3];
    const float* bk1 = (const float*)d_in[4];
    const float* Wv1 = (const float*)d_in[5];
    const float* bv1 = (const float*)d_in[6];
    const float* Wq2 = (const float*)d_in[7];
    const float* bq2 = (const float*)d_in[8];
    const float* Wk2 = (const float*)d_in[9];
    const float* bk2 = (const float*)d_in[10];
    const float* Wv2 = (const float*)d_in[11];
    const float* bv2 = (const float*)d_in[12];
    const float* Wc  = (const float*)d_in[13];
    const float* bc  = (const float*)d_in[14];
    const float* gam = (const float*)d_in[15];
    const float* bet = (const float*)d_in[16];
    float* out = (float*)d_out;

    proj_kernel<<<dim3(16, 20, BATCH), 256>>>(x,
        Wq1, bq1, Wk1, bk1, Wv1, bv1,
        Wq2, bq2, Wk2, bk2, Wv2, bv2);

    round_w_kernel<<<256, 256>>>(Wc);

    qk_exp_kernel<<<dim3(32, 64, 8), 256>>>();

    const int pv_smem = PV_SMEM_FLOATS * (int)sizeof(float);   // 110592 B
    cudaFuncSetAttribute(pv_mma_kernel,
                         cudaFuncAttributeMaxDynamicSharedMemorySize, pv_smem);
    pv_mma_kernel<<<dim3(32, 8), 256, pv_smem>>>();

    const int oc_smem = OC_SMEM_FLOATS * (int)sizeof(float);   // 71680 B
    cudaFuncSetAttribute(outconv_mma_kernel,
                         cudaFuncAttributeMaxDynamicSharedMemorySize, oc_smem);
    outconv_mma_kernel<<<dim3(32, 4, BATCH), 256, oc_smem>>>(bc, out, gam, bet);
}